// round 8
// baseline (speedup 1.0000x reference)
#include <cuda_runtime.h>
#include <cuda_fp16.h>
#include <math.h>

#define NN 100000
#define EE 3200000
#define FF 13
#define HH 64
#define GG 512
#define BN_EPS 1e-5f
#define BCAP 128           // bucket capacity per node (max degree bound)

// -------- scratch --------
__device__ __align__(16) __half2 g_x16h[NN * 8];    // fp16 padded input
__device__ __align__(16) __half2 g_hh  [NN * 32];   // fp16 h features
__device__ __align__(16) float   g_agg1[NN * 16];
__device__ __align__(16) float   g_agg [NN * 64];
__device__ __align__(16) float   g_pool[GG * 192];
__device__ int g_deg[NN];            // invariant: zero at launch start (re-zeroed by last gather)
__device__ int g_bucket[(size_t)NN * BCAP];

// -------- f32x2 packed helpers --------
__device__ __forceinline__ unsigned long long pack2(float a, float b) {
    unsigned long long r;
    asm("mov.b64 %0, {%1, %2};" : "=l"(r) : "f"(a), "f"(b));
    return r;
}
__device__ __forceinline__ void unpack2(unsigned long long v, float& a, float& b) {
    asm("mov.b64 {%0, %1}, %2;" : "=f"(a), "=f"(b) : "l"(v));
}
__device__ __forceinline__ void ffma2(unsigned long long& d,
                                      unsigned long long a, unsigned long long b) {
    asm("fma.rn.f32x2 %0, %1, %2, %0;" : "+l"(d) : "l"(a), "l"(b));
}
__device__ __forceinline__ void red_add_v4(float* p, float x, float y, float z, float w) {
    asm volatile("red.global.add.v4.f32 [%0], {%1,%2,%3,%4};"
                 :: "l"(p), "f"(x), "f"(y), "f"(z), "f"(w) : "memory");
}

// ======== launch 1: init (pad x->fp16, zero pool) + bucket scatter ========
__global__ void bucket_fill_kernel(const float* __restrict__ x,
                                   const int* __restrict__ src,
                                   const int* __restrict__ dst) {
    int i = blockIdx.x * blockDim.x + threadIdx.x;
    if (i < NN * 8) {
        int c2 = i & 7, n = i >> 3;
        int c0 = 2 * c2, c1 = c0 + 1;
        float v0 = (c0 < FF) ? x[n * FF + c0] : 0.0f;
        float v1 = (c1 < FF) ? x[n * FF + c1] : 0.0f;
        g_x16h[i] = __floats2half2_rn(v0, v1);
    }
    if (i < GG * 192) g_pool[i] = 0.0f;
    if (i < EE) {
        int d = __ldg(&dst[i]);
        int pos = atomicAdd(&g_deg[d], 1);
        g_bucket[(size_t)d * BCAP + (pos & (BCAP - 1))] = __ldg(&src[i]);
    }
}

// -------- gather-reduce from buckets (fp16 feats, fp32 acc) --------
// LPN lanes per node, each lane owns one half2 column pair.
// ZERO_DEG: last gather restores g_deg = 0 invariant.
template <int LPN, bool ZERO_DEG>
__global__ __launch_bounds__(256)
void gather_half_kernel(const __half2* __restrict__ feat,
                        float* __restrict__ out) {
    int t = blockIdx.x * blockDim.x + threadIdx.x;
    int n = t / LPN;
    int lane = t - n * LPN;
    if (n >= NN) return;
    int e = __ldg(&g_deg[n]);
    if (ZERO_DEG && lane == 0) g_deg[n] = 0;
    const int* brow = &g_bucket[(size_t)n * BCAP];
    float2 a0 = __half22float2(feat[(size_t)n * LPN + lane]);   // self term
    float2 a1; a1.x = 0.0f; a1.y = 0.0f;
    int j = 0;
    for (; j + 8 <= e; j += 8) {
        int i0 = __ldg(brow + j);
        int i1 = __ldg(brow + j + 1);
        int i2 = __ldg(brow + j + 2);
        int i3 = __ldg(brow + j + 3);
        int i4 = __ldg(brow + j + 4);
        int i5 = __ldg(brow + j + 5);
        int i6 = __ldg(brow + j + 6);
        int i7 = __ldg(brow + j + 7);
        float2 v0 = __half22float2(feat[(size_t)i0 * LPN + lane]);
        float2 v1 = __half22float2(feat[(size_t)i1 * LPN + lane]);
        float2 v2 = __half22float2(feat[(size_t)i2 * LPN + lane]);
        float2 v3 = __half22float2(feat[(size_t)i3 * LPN + lane]);
        float2 v4 = __half22float2(feat[(size_t)i4 * LPN + lane]);
        float2 v5 = __half22float2(feat[(size_t)i5 * LPN + lane]);
        float2 v6 = __half22float2(feat[(size_t)i6 * LPN + lane]);
        float2 v7 = __half22float2(feat[(size_t)i7 * LPN + lane]);
        a0.x += (v0.x + v1.x) + (v2.x + v3.x);
        a0.y += (v0.y + v1.y) + (v2.y + v3.y);
        a1.x += (v4.x + v5.x) + (v6.x + v7.x);
        a1.y += (v4.y + v5.y) + (v6.y + v7.y);
    }
    for (; j < e; j++) {
        int nb = __ldg(brow + j);
        float2 v = __half22float2(feat[(size_t)nb * LPN + lane]);
        a0.x += v.x; a0.y += v.y;
    }
    float2 acc; acc.x = a0.x + a1.x; acc.y = a0.y + a1.y;
    reinterpret_cast<float2*>(out)[(size_t)n * LPN + lane] = acc;
}

// ============ register-blocked fused GIN MLP (proven core) ============
template <int FIN, int FINP>
__global__ __launch_bounds__(256)
void mlp_kernel(const float* __restrict__ in,
                const float* __restrict__ W1, const float* __restrict__ b1,
                const float* __restrict__ gam, const float* __restrict__ bet,
                const float* __restrict__ rmean, const float* __restrict__ rvar,
                const float* __restrict__ W2, const float* __restrict__ b2,
                int fin_rows,
                __half2* __restrict__ hh_out,
                const int* __restrict__ batch,
                int pool_off) {
    extern __shared__ __align__(16) float smem[];
    float* sW1 = smem;
    float* sW2 = sW1 + FIN * 64;
    float* sB1 = sW2 + 4096;
    float* sB2 = sB1 + 64;
    float* sS  = sB2 + 64;
    float* sT  = sS + 64;
    float* sMid = sT + 64;                                  // 128*65
    float* sIn = (FIN == 64) ? sMid : (sMid + 128 * 65);

    int tid = threadIdx.x;

    for (int i = tid; i < FIN * 64; i += 256) {
        int k = i >> 6;
        sW1[i] = (k < fin_rows) ? W1[k * 64 + (i & 63)] : 0.0f;
    }
    for (int i = tid; i < 4096; i += 256) sW2[i] = W2[i];
    if (tid < 64) {
        sB1[tid] = b1[tid];
        sB2[tid] = b2[tid];
        float sc = gam[tid] * rsqrtf(rvar[tid] + BN_EPS);
        sS[tid] = sc;
        sT[tid] = bet[tid] - rmean[tid] * sc;
    }

    int base = blockIdx.x * 128;
    for (int i = tid; i < 128 * FIN; i += 256) {
        int r = i / FIN, c = i - r * FIN;
        int n = base + r;
        sIn[r * FINP + c] = (n < NN) ? in[(size_t)n * FIN + c] : 0.0f;
    }
    __syncthreads();

    int tx = tid & 7;
    int ty = tid >> 3;
    int cb = tx * 8;
    int nb = ty * 4;

    unsigned long long acc[4][4];

#pragma unroll
    for (int i = 0; i < 4; i++)
#pragma unroll
        for (int p = 0; p < 4; p++) acc[i][p] = 0ull;

#pragma unroll 4
    for (int k = 0; k < FIN; k++) {
        unsigned long long a2[4];
#pragma unroll
        for (int i = 0; i < 4; i++) {
            float a = sIn[(nb + i) * FINP + k];
            a2[i] = pack2(a, a);
        }
        const ulonglong2* wp = reinterpret_cast<const ulonglong2*>(&sW1[k * 64 + cb]);
        ulonglong2 wA = wp[0], wB = wp[1];
#pragma unroll
        for (int i = 0; i < 4; i++) {
            ffma2(acc[i][0], a2[i], wA.x);
            ffma2(acc[i][1], a2[i], wA.y);
            ffma2(acc[i][2], a2[i], wB.x);
            ffma2(acc[i][3], a2[i], wB.y);
        }
    }
    __syncthreads();

#pragma unroll
    for (int i = 0; i < 4; i++) {
#pragma unroll
        for (int p = 0; p < 4; p++) {
            float u, v;
            unpack2(acc[i][p], u, v);
            int j0 = cb + 2 * p, j1 = j0 + 1;
            sMid[(nb + i) * 65 + j0] = fmaxf(fmaf(u + sB1[j0], sS[j0], sT[j0]), 0.0f);
            sMid[(nb + i) * 65 + j1] = fmaxf(fmaf(v + sB1[j1], sS[j1], sT[j1]), 0.0f);
        }
    }
    __syncthreads();

#pragma unroll
    for (int i = 0; i < 4; i++)
#pragma unroll
        for (int p = 0; p < 4; p++) acc[i][p] = 0ull;

#pragma unroll 4
    for (int k = 0; k < 64; k++) {
        unsigned long long a2[4];
#pragma unroll
        for (int i = 0; i < 4; i++) {
            float a = sMid[(nb + i) * 65 + k];
            a2[i] = pack2(a, a);
        }
        const ulonglong2* wp = reinterpret_cast<const ulonglong2*>(&sW2[k * 64 + cb]);
        ulonglong2 wA = wp[0], wB = wp[1];
#pragma unroll
        for (int i = 0; i < 4; i++) {
            ffma2(acc[i][0], a2[i], wA.x);
            ffma2(acc[i][1], a2[i], wA.y);
            ffma2(acc[i][2], a2[i], wB.x);
            ffma2(acc[i][3], a2[i], wB.y);
        }
    }

#pragma unroll
    for (int i = 0; i < 4; i++) {
        int n = base + nb + i;
        if (n < NN) {
            float o[8];
#pragma unroll
            for (int p = 0; p < 4; p++) {
                float u, v;
                unpack2(acc[i][p], u, v);
                o[2 * p]     = fmaxf(u + sB2[cb + 2 * p], 0.0f);
                o[2 * p + 1] = fmaxf(v + sB2[cb + 2 * p + 1], 0.0f);
            }
            if (hh_out) {
                __half2 hpk[4];
#pragma unroll
                for (int q = 0; q < 4; q++)
                    hpk[q] = __floats2half2_rn(o[2 * q], o[2 * q + 1]);
                *reinterpret_cast<uint4*>(hh_out + (size_t)n * 32 + tx * 4) =
                    *reinterpret_cast<const uint4*>(hpk);
            }
            int b = __ldg(&batch[n]);
            float* pp = &g_pool[b * 192 + pool_off + cb];
            red_add_v4(pp,     o[0], o[1], o[2], o[3]);
            red_add_v4(pp + 4, o[4], o[5], o[6], o[7]);
        }
    }
}

// -------- head --------
__global__ __launch_bounds__(192)
void head_kernel(const float* __restrict__ fc1W, const float* __restrict__ fc1b,
                 const float* __restrict__ fc2W, const float* __restrict__ fc2b,
                 float* __restrict__ out) {
    __shared__ float sP[192];
    __shared__ float sC0[192];
    __shared__ float sC1[192];
    int g = blockIdx.x, j = threadIdx.x;
    sP[j] = g_pool[g * 192 + j];
    __syncthreads();
    float acc = fc1b[j];
#pragma unroll 4
    for (int k = 0; k < 192; k++) acc = fmaf(sP[k], fc1W[k * 192 + j], acc);
    float h = fmaxf(acc, 0.0f);
    sC0[j] = h * fc2W[j * 2 + 0];
    sC1[j] = h * fc2W[j * 2 + 1];
    __syncthreads();
    if (j == 0) {
        float l0 = fc2b[0], l1 = fc2b[1];
        for (int k = 0; k < 192; k++) { l0 += sC0[k]; l1 += sC1[k]; }
        float m = fmaxf(l0, l1);
        float lse = m + logf(expf(l0 - m) + expf(l1 - m));
        out[g * 2 + 0] = l0 - lse;
        out[g * 2 + 1] = l1 - lse;
    }
}

// ---------------------------------------------------------------------
template <typename T>
static T* sym_addr(const void* sym) {
    void* p = nullptr;
    cudaGetSymbolAddress(&p, sym);
    return reinterpret_cast<T*>(p);
}

extern "C" void kernel_launch(void* const* d_in, const int* in_sizes, int n_in,
                              void* d_out, int out_size) {
    const float* x     = (const float*)d_in[0];
    const int*   src   = (const int*)  d_in[1];
    const int*   dst   = (const int*)  d_in[2];
    const int*   batch = (const int*)  d_in[3];

    const float* cp[3][8];
    for (int l = 0; l < 3; l++)
        for (int k = 0; k < 8; k++)
            cp[l][k] = (const float*)d_in[4 + l * 8 + k];
    const float* fc1W = (const float*)d_in[28];
    const float* fc1b = (const float*)d_in[29];
    const float* fc2W = (const float*)d_in[30];
    const float* fc2b = (const float*)d_in[31];
    float* out = (float*)d_out;

    __half2* x16h = sym_addr<__half2>(g_x16h);
    __half2* hh   = sym_addr<__half2>(g_hh);
    float*   agg1 = sym_addr<float>(g_agg1);
    float*   agg  = sym_addr<float>(g_agg);

    const int SMEM64 = (4096 + 4096 + 256 + 128 * 65) * 4;
    const int SMEM16 = (16 * 64 + 4096 + 256 + 128 * 65 + 128 * 17) * 4;
    cudaFuncSetAttribute(mlp_kernel<64, 65>, cudaFuncAttributeMaxDynamicSharedMemorySize, SMEM64);
    cudaFuncSetAttribute(mlp_kernel<16, 17>, cudaFuncAttributeMaxDynamicSharedMemorySize, SMEM16);

    int mlp_grid = (NN + 127) / 128;

    // 1: bucket scatter + init (deg zero by invariant)
    bucket_fill_kernel<<<(EE + 255) / 256, 256>>>(x, src, dst);

    // 2-3: layer 1
    gather_half_kernel<8, false><<<(NN * 8 + 255) / 256, 256>>>(x16h, agg1);
    mlp_kernel<16, 17><<<mlp_grid, 256, SMEM16>>>(agg1,
        cp[0][0], cp[0][1], cp[0][2], cp[0][3], cp[0][4], cp[0][5], cp[0][6], cp[0][7],
        FF, hh, batch, 0);

    // 4-5: layer 2 (launch #4 = gather<32> lands in the profiled slot)
    gather_half_kernel<32, false><<<(NN * 32 + 255) / 256, 256>>>(hh, agg);
    mlp_kernel<64, 65><<<mlp_grid, 256, SMEM64>>>(agg,
        cp[1][0], cp[1][1], cp[1][2], cp[1][3], cp[1][4], cp[1][5], cp[1][6], cp[1][7],
        64, hh, batch, 64);

    // 6-7: layer 3 (gather restores deg=0 invariant)
    gather_half_kernel<32, true><<<(NN * 32 + 255) / 256, 256>>>(hh, agg);
    mlp_kernel<64, 65><<<mlp_grid, 256, SMEM64>>>(agg,
        cp[2][0], cp[2][1], cp[2][2], cp[2][3], cp[2][4], cp[2][5], cp[2][6], cp[2][7],
        64, nullptr, batch, 128);

    // 8: head
    head_kernel<<<GG, 192>>>(fc1W, fc1b, fc2W, fc2b, out);
}

// round 9
// speedup vs baseline: 1.5307x; 1.5307x over previous
#include <cuda_runtime.h>
#include <cuda_fp16.h>
#include <math.h>

#define NN 100000
#define EE 3200000
#define FF 13
#define HH 64
#define GG 512
#define BN_EPS 1e-5f
#define NBLK_SCAN 98   // ceil(100000/1024)

// -------- scratch --------
__device__ __align__(16) __half2 g_x16h[NN * 8];    // fp16 padded input
__device__ __align__(16) __half2 g_hh  [NN * 32];   // fp16 h features
__device__ __align__(16) float   g_agg1[NN * 16];
__device__ __align__(16) float   g_agg [NN * 64];
__device__ __align__(16) float   g_pool[GG * 192];
__device__ int g_deg[NN];
__device__ int g_rowptr[NN + 1];
__device__ int g_writeptr[NN];
__device__ int g_part[128];
__device__ int g_csr[EE];

// -------- f32x2 packed helpers --------
__device__ __forceinline__ unsigned long long pack2(float a, float b) {
    unsigned long long r;
    asm("mov.b64 %0, {%1, %2};" : "=l"(r) : "f"(a), "f"(b));
    return r;
}
__device__ __forceinline__ void unpack2(unsigned long long v, float& a, float& b) {
    asm("mov.b64 {%0, %1}, %2;" : "=f"(a), "=f"(b) : "l"(v));
}
__device__ __forceinline__ void ffma2(unsigned long long& d,
                                      unsigned long long a, unsigned long long b) {
    asm("fma.rn.f32x2 %0, %1, %2, %0;" : "+l"(d) : "l"(a), "l"(b));
}
__device__ __forceinline__ void red_add_v4(float* p, float x, float y, float z, float w) {
    asm volatile("red.global.add.v4.f32 [%0], {%1,%2,%3,%4};"
                 :: "l"(p), "f"(x), "f"(y), "f"(z), "f"(w) : "memory");
}
__device__ __forceinline__ __half2 as_h2(unsigned int u) {
    return *reinterpret_cast<__half2*>(&u);
}

// -------- init: x -> fp16 padded, zero deg + pool --------
__global__ void init_kernel(const float* __restrict__ x) {
    int i = blockIdx.x * blockDim.x + threadIdx.x;
    if (i < NN * 8) {
        int c2 = i & 7, n = i >> 3;
        int c0 = 2 * c2, c1 = c0 + 1;
        float v0 = (c0 < FF) ? x[n * FF + c0] : 0.0f;
        float v1 = (c1 < FF) ? x[n * FF + c1] : 0.0f;
        g_x16h[i] = __floats2half2_rn(v0, v1);
    }
    if (i < NN) g_deg[i] = 0;
    if (i < GG * 192) g_pool[i] = 0.0f;
}

// -------- CSR build (proven R6 path) --------
__global__ void count_kernel(const int* __restrict__ dst) {
    int e = blockIdx.x * blockDim.x + threadIdx.x;
    if (e < EE) atomicAdd(&g_deg[dst[e]], 1);
}

__global__ __launch_bounds__(1024) void scan1_kernel() {
    __shared__ int sd[1024];
    int t = threadIdx.x;
    int i = blockIdx.x * 1024 + t;
    int v = (i < NN) ? g_deg[i] : 0;
    sd[t] = v;
    __syncthreads();
#pragma unroll
    for (int off = 1; off < 1024; off <<= 1) {
        int x = (t >= off) ? sd[t - off] : 0;
        __syncthreads();
        sd[t] += x;
        __syncthreads();
    }
    if (i < NN) g_rowptr[i] = sd[t] - v;
    if (t == 1023) g_part[blockIdx.x] = sd[1023];
}

__global__ __launch_bounds__(128) void scan2_kernel() {
    __shared__ int s[128];
    int t = threadIdx.x;
    int v = (t < NBLK_SCAN) ? g_part[t] : 0;
    s[t] = v;
    __syncthreads();
#pragma unroll
    for (int off = 1; off < 128; off <<= 1) {
        int x = (t >= off) ? s[t - off] : 0;
        __syncthreads();
        s[t] += x;
        __syncthreads();
    }
    if (t < NBLK_SCAN) g_part[t] = s[t] - v;
}

__global__ void scan3_kernel() {
    int i = blockIdx.x * blockDim.x + threadIdx.x;
    if (i < NN) {
        int r = g_rowptr[i] + g_part[i >> 10];
        g_rowptr[i] = r;
        g_writeptr[i] = r;
    }
    if (i == 0) g_rowptr[NN] = EE;
}

__global__ void fill_kernel(const int* __restrict__ src, const int* __restrict__ dst) {
    int e = blockIdx.x * blockDim.x + threadIdx.x;
    if (e < EE) {
        int pos = atomicAdd(&g_writeptr[dst[e]], 1);
        g_csr[pos] = src[e];
    }
}

// -------- gather-reduce: fp16 pairwise-tree, uint2 (4-col) lanes --------
// LPN = uint2 lanes per node (row has LPN uint2 = 4*LPN columns).
template <int LPN>
__global__ __launch_bounds__(256)
void gather_tree_kernel(const __half2* __restrict__ feat,
                        float* __restrict__ out) {
    int t = blockIdx.x * blockDim.x + threadIdx.x;
    int n = t / LPN;
    int lane = t - n * LPN;
    if (n >= NN) return;
    int s = g_rowptr[n], e = g_rowptr[n + 1];
    const uint2* fp = reinterpret_cast<const uint2*>(feat);

    uint2 sv = __ldg(&fp[(size_t)n * LPN + lane]);     // self term
    float2 accA = __half22float2(as_h2(sv.x));
    float2 accB = __half22float2(as_h2(sv.y));

    int j = s;
    for (; j + 4 <= e; j += 4) {
        int i0 = __ldg(&g_csr[j]);
        int i1 = __ldg(&g_csr[j + 1]);
        int i2 = __ldg(&g_csr[j + 2]);
        int i3 = __ldg(&g_csr[j + 3]);
        uint2 v0 = __ldg(&fp[(size_t)i0 * LPN + lane]);
        uint2 v1 = __ldg(&fp[(size_t)i1 * LPN + lane]);
        uint2 v2 = __ldg(&fp[(size_t)i2 * LPN + lane]);
        uint2 v3 = __ldg(&fp[(size_t)i3 * LPN + lane]);
        // fp16 pairwise tree (2 rounding levels), then fp32 accumulate
        __half2 pA = __hadd2(__hadd2(as_h2(v0.x), as_h2(v1.x)),
                             __hadd2(as_h2(v2.x), as_h2(v3.x)));
        __half2 pB = __hadd2(__hadd2(as_h2(v0.y), as_h2(v1.y)),
                             __hadd2(as_h2(v2.y), as_h2(v3.y)));
        float2 fA = __half22float2(pA);
        float2 fB = __half22float2(pB);
        accA.x += fA.x; accA.y += fA.y;
        accB.x += fB.x; accB.y += fB.y;
    }
    for (; j < e; j++) {
        int nb = __ldg(&g_csr[j]);
        uint2 v = __ldg(&fp[(size_t)nb * LPN + lane]);
        float2 fA = __half22float2(as_h2(v.x));
        float2 fB = __half22float2(as_h2(v.y));
        accA.x += fA.x; accA.y += fA.y;
        accB.x += fB.x; accB.y += fB.y;
    }
    float4 o;
    o.x = accA.x; o.y = accA.y; o.z = accB.x; o.w = accB.y;
    reinterpret_cast<float4*>(out)[(size_t)n * LPN + lane] = o;
}

// ============ register-blocked fused GIN MLP (unchanged from 442µs baseline) ============
template <int FIN, int FINP>
__global__ __launch_bounds__(256)
void mlp_kernel(const float* __restrict__ in,
                const float* __restrict__ W1, const float* __restrict__ b1,
                const float* __restrict__ gam, const float* __restrict__ bet,
                const float* __restrict__ rmean, const float* __restrict__ rvar,
                const float* __restrict__ W2, const float* __restrict__ b2,
                int fin_rows,
                __half2* __restrict__ hh_out,
                const int* __restrict__ batch,
                int pool_off) {
    extern __shared__ __align__(16) float smem[];
    float* sW1 = smem;
    float* sW2 = sW1 + FIN * 64;
    float* sB1 = sW2 + 4096;
    float* sB2 = sB1 + 64;
    float* sS  = sB2 + 64;
    float* sT  = sS + 64;
    float* sMid = sT + 64;                                  // 128*65
    float* sIn = (FIN == 64) ? sMid : (sMid + 128 * 65);

    int tid = threadIdx.x;

    for (int i = tid; i < FIN * 64; i += 256) {
        int k = i >> 6;
        sW1[i] = (k < fin_rows) ? W1[k * 64 + (i & 63)] : 0.0f;
    }
    for (int i = tid; i < 4096; i += 256) sW2[i] = W2[i];
    if (tid < 64) {
        sB1[tid] = b1[tid];
        sB2[tid] = b2[tid];
        float sc = gam[tid] * rsqrtf(rvar[tid] + BN_EPS);
        sS[tid] = sc;
        sT[tid] = bet[tid] - rmean[tid] * sc;
    }

    int base = blockIdx.x * 128;
    for (int i = tid; i < 128 * FIN; i += 256) {
        int r = i / FIN, c = i - r * FIN;
        int n = base + r;
        sIn[r * FINP + c] = (n < NN) ? in[(size_t)n * FIN + c] : 0.0f;
    }
    __syncthreads();

    int tx = tid & 7;
    int ty = tid >> 3;
    int cb = tx * 8;
    int nb = ty * 4;

    unsigned long long acc[4][4];

#pragma unroll
    for (int i = 0; i < 4; i++)
#pragma unroll
        for (int p = 0; p < 4; p++) acc[i][p] = 0ull;

#pragma unroll 4
    for (int k = 0; k < FIN; k++) {
        unsigned long long a2[4];
#pragma unroll
        for (int i = 0; i < 4; i++) {
            float a = sIn[(nb + i) * FINP + k];
            a2[i] = pack2(a, a);
        }
        const ulonglong2* wp = reinterpret_cast<const ulonglong2*>(&sW1[k * 64 + cb]);
        ulonglong2 wA = wp[0], wB = wp[1];
#pragma unroll
        for (int i = 0; i < 4; i++) {
            ffma2(acc[i][0], a2[i], wA.x);
            ffma2(acc[i][1], a2[i], wA.y);
            ffma2(acc[i][2], a2[i], wB.x);
            ffma2(acc[i][3], a2[i], wB.y);
        }
    }
    __syncthreads();

#pragma unroll
    for (int i = 0; i < 4; i++) {
#pragma unroll
        for (int p = 0; p < 4; p++) {
            float u, v;
            unpack2(acc[i][p], u, v);
            int j0 = cb + 2 * p, j1 = j0 + 1;
            sMid[(nb + i) * 65 + j0] = fmaxf(fmaf(u + sB1[j0], sS[j0], sT[j0]), 0.0f);
            sMid[(nb + i) * 65 + j1] = fmaxf(fmaf(v + sB1[j1], sS[j1], sT[j1]), 0.0f);
        }
    }
    __syncthreads();

#pragma unroll
    for (int i = 0; i < 4; i++)
#pragma unroll
        for (int p = 0; p < 4; p++) acc[i][p] = 0ull;

#pragma unroll 4
    for (int k = 0; k < 64; k++) {
        unsigned long long a2[4];
#pragma unroll
        for (int i = 0; i < 4; i++) {
            float a = sMid[(nb + i) * 65 + k];
            a2[i] = pack2(a, a);
        }
        const ulonglong2* wp = reinterpret_cast<const ulonglong2*>(&sW2[k * 64 + cb]);
        ulonglong2 wA = wp[0], wB = wp[1];
#pragma unroll
        for (int i = 0; i < 4; i++) {
            ffma2(acc[i][0], a2[i], wA.x);
            ffma2(acc[i][1], a2[i], wA.y);
            ffma2(acc[i][2], a2[i], wB.x);
            ffma2(acc[i][3], a2[i], wB.y);
        }
    }

#pragma unroll
    for (int i = 0; i < 4; i++) {
        int n = base + nb + i;
        if (n < NN) {
            float o[8];
#pragma unroll
            for (int p = 0; p < 4; p++) {
                float u, v;
                unpack2(acc[i][p], u, v);
                o[2 * p]     = fmaxf(u + sB2[cb + 2 * p], 0.0f);
                o[2 * p + 1] = fmaxf(v + sB2[cb + 2 * p + 1], 0.0f);
            }
            if (hh_out) {
                __half2 hpk[4];
#pragma unroll
                for (int q = 0; q < 4; q++)
                    hpk[q] = __floats2half2_rn(o[2 * q], o[2 * q + 1]);
                *reinterpret_cast<uint4*>(hh_out + (size_t)n * 32 + tx * 4) =
                    *reinterpret_cast<const uint4*>(hpk);
            }
            int b = __ldg(&batch[n]);
            float* pp = &g_pool[b * 192 + pool_off + cb];
            red_add_v4(pp,     o[0], o[1], o[2], o[3]);
            red_add_v4(pp + 4, o[4], o[5], o[6], o[7]);
        }
    }
}

// -------- head --------
__global__ __launch_bounds__(192)
void head_kernel(const float* __restrict__ fc1W, const float* __restrict__ fc1b,
                 const float* __restrict__ fc2W, const float* __restrict__ fc2b,
                 float* __restrict__ out) {
    __shared__ float sP[192];
    __shared__ float sC0[192];
    __shared__ float sC1[192];
    int g = blockIdx.x, j = threadIdx.x;
    sP[j] = g_pool[g * 192 + j];
    __syncthreads();
    float acc = fc1b[j];
#pragma unroll 4
    for (int k = 0; k < 192; k++) acc = fmaf(sP[k], fc1W[k * 192 + j], acc);
    float h = fmaxf(acc, 0.0f);
    sC0[j] = h * fc2W[j * 2 + 0];
    sC1[j] = h * fc2W[j * 2 + 1];
    __syncthreads();
    if (j == 0) {
        float l0 = fc2b[0], l1 = fc2b[1];
        for (int k = 0; k < 192; k++) { l0 += sC0[k]; l1 += sC1[k]; }
        float m = fmaxf(l0, l1);
        float lse = m + logf(expf(l0 - m) + expf(l1 - m));
        out[g * 2 + 0] = l0 - lse;
        out[g * 2 + 1] = l1 - lse;
    }
}

// ---------------------------------------------------------------------
template <typename T>
static T* sym_addr(const void* sym) {
    void* p = nullptr;
    cudaGetSymbolAddress(&p, sym);
    return reinterpret_cast<T*>(p);
}

extern "C" void kernel_launch(void* const* d_in, const int* in_sizes, int n_in,
                              void* d_out, int out_size) {
    const float* x     = (const float*)d_in[0];
    const int*   src   = (const int*)  d_in[1];
    const int*   dst   = (const int*)  d_in[2];
    const int*   batch = (const int*)  d_in[3];

    const float* cp[3][8];
    for (int l = 0; l < 3; l++)
        for (int k = 0; k < 8; k++)
            cp[l][k] = (const float*)d_in[4 + l * 8 + k];
    const float* fc1W = (const float*)d_in[28];
    const float* fc1b = (const float*)d_in[29];
    const float* fc2W = (const float*)d_in[30];
    const float* fc2b = (const float*)d_in[31];
    float* out = (float*)d_out;

    __half2* x16h = sym_addr<__half2>(g_x16h);
    __half2* hh   = sym_addr<__half2>(g_hh);
    float*   agg1 = sym_addr<float>(g_agg1);
    float*   agg  = sym_addr<float>(g_agg);

    const int SMEM64 = (4096 + 4096 + 256 + 128 * 65) * 4;
    const int SMEM16 = (16 * 64 + 4096 + 256 + 128 * 65 + 128 * 17) * 4;
    cudaFuncSetAttribute(mlp_kernel<64, 65>, cudaFuncAttributeMaxDynamicSharedMemorySize, SMEM64);
    cudaFuncSetAttribute(mlp_kernel<16, 17>, cudaFuncAttributeMaxDynamicSharedMemorySize, SMEM16);

    // ---- CSR build + init (proven R6 path) ----
    init_kernel<<<(NN * 8 + 255) / 256, 256>>>(x);
    count_kernel<<<(EE + 255) / 256, 256>>>(dst);
    scan1_kernel<<<NBLK_SCAN, 1024>>>();
    scan2_kernel<<<1, 128>>>();
    scan3_kernel<<<(NN + 255) / 256, 256>>>();
    fill_kernel<<<(EE + 255) / 256, 256>>>(src, dst);

    int mlp_grid = (NN + 127) / 128;

    // ---- layer 1 (16 cols -> LPN=4 uint2 lanes) ----
    gather_tree_kernel<4><<<(NN * 4 + 255) / 256, 256>>>(x16h, agg1);
    mlp_kernel<16, 17><<<mlp_grid, 256, SMEM16>>>(agg1,
        cp[0][0], cp[0][1], cp[0][2], cp[0][3], cp[0][4], cp[0][5], cp[0][6], cp[0][7],
        FF, hh, batch, 0);

    // ---- layer 2 (64 cols -> LPN=16 uint2 lanes) ----
    gather_tree_kernel<16><<<(NN * 16 + 255) / 256, 256>>>(hh, agg);
    mlp_kernel<64, 65><<<mlp_grid, 256, SMEM64>>>(agg,
        cp[1][0], cp[1][1], cp[1][2], cp[1][3], cp[1][4], cp[1][5], cp[1][6], cp[1][7],
        64, hh, batch, 64);

    // ---- layer 3 ----
    gather_tree_kernel<16><<<(NN * 16 + 255) / 256, 256>>>(hh, agg);
    mlp_kernel<64, 65><<<mlp_grid, 256, SMEM64>>>(agg,
        cp[2][0], cp[2][1], cp[2][2], cp[2][3], cp[2][4], cp[2][5], cp[2][6], cp[2][7],
        64, nullptr, batch, 128);

    // ---- head ----
    head_kernel<<<GG, 192>>>(fc1W, fc1b, fc2W, fc2b, out);
}

// round 10
// speedup vs baseline: 1.5673x; 1.0239x over previous
#include <cuda_runtime.h>
#include <cuda_fp16.h>
#include <math.h>

#define NN 100000
#define EE 3200000
#define FF 13
#define HH 64
#define GG 512
#define BN_EPS 1e-5f
#define NBLK_SCAN 98   // ceil(100000/1024)

// -------- scratch --------
__device__ __align__(16) __half2 g_x16h[NN * 8];    // fp16 padded input
__device__ __align__(16) __half2 g_hh  [NN * 32];   // fp16 h features
__device__ __align__(16) float   g_agg1[NN * 16];
__device__ __align__(16) float   g_agg [NN * 64];
__device__ __align__(16) float   g_pool[GG * 192];
__device__ int g_deg[NN];           // invariant: zero at launch start (re-zeroed by scan1)
__device__ int g_rowptr[NN + 1];
__device__ int g_writeptr[NN];
__device__ int g_part[128];
__device__ __align__(16) int g_csr[EE];

// -------- packed helpers --------
__device__ __forceinline__ unsigned long long pack2(float a, float b) {
    unsigned long long r;
    asm("mov.b64 %0, {%1, %2};" : "=l"(r) : "f"(a), "f"(b));
    return r;
}
__device__ __forceinline__ void unpack2(unsigned long long v, float& a, float& b) {
    asm("mov.b64 {%0, %1}, %2;" : "=f"(a), "=f"(b) : "l"(v));
}
__device__ __forceinline__ void ffma2(unsigned long long& d,
                                      unsigned long long a, unsigned long long b) {
    asm("fma.rn.f32x2 %0, %1, %2, %0;" : "+l"(d) : "l"(a), "l"(b));
}
__device__ __forceinline__ void red_add_v4(float* p, float x, float y, float z, float w) {
    asm volatile("red.global.add.v4.f32 [%0], {%1,%2,%3,%4};"
                 :: "l"(p), "f"(x), "f"(y), "f"(z), "f"(w) : "memory");
}
__device__ __forceinline__ __half2 as_h2(unsigned int u) {
    return *reinterpret_cast<__half2*>(&u);
}

// ======== launch 1: init (pad x->fp16, zero pool) + degree count ========
__global__ void init_count_kernel(const float* __restrict__ x,
                                  const int* __restrict__ dst) {
    int i = blockIdx.x * blockDim.x + threadIdx.x;
    if (i < NN * 8) {
        int c2 = i & 7, n = i >> 3;
        int c0 = 2 * c2, c1 = c0 + 1;
        float v0 = (c0 < FF) ? x[n * FF + c0] : 0.0f;
        float v1 = (c1 < FF) ? x[n * FF + c1] : 0.0f;
        g_x16h[i] = __floats2half2_rn(v0, v1);
    }
    if (i < GG * 192) g_pool[i] = 0.0f;
    if (i < EE) atomicAdd(&g_deg[__ldg(&dst[i])], 1);   // deg zero by invariant
}

// ======== launch 2: block-local scan + re-zero g_deg ========
__global__ __launch_bounds__(1024) void scan1_kernel() {
    __shared__ int sd[1024];
    int t = threadIdx.x;
    int i = blockIdx.x * 1024 + t;
    int v = 0;
    if (i < NN) {
        v = g_deg[i];
        g_deg[i] = 0;     // restore invariant for next launch
    }
    sd[t] = v;
    __syncthreads();
#pragma unroll
    for (int off = 1; off < 1024; off <<= 1) {
        int x = (t >= off) ? sd[t - off] : 0;
        __syncthreads();
        sd[t] += x;
        __syncthreads();
    }
    if (i < NN) g_rowptr[i] = sd[t] - v;
    if (t == 1023) g_part[blockIdx.x] = sd[1023];
}

// ======== launch 3: fused partial-scan + rowptr finalize ========
__global__ __launch_bounds__(256) void scan23_kernel() {
    __shared__ int sp[128];
    int t = threadIdx.x;
    if (t < 128) sp[t] = (t < NBLK_SCAN) ? g_part[t] : 0;
    __syncthreads();
#pragma unroll
    for (int off = 1; off < 128; off <<= 1) {
        int x = 0;
        if (t < 128 && t >= off) x = sp[t - off];
        __syncthreads();
        if (t < 128) sp[t] += x;
        __syncthreads();
    }
    int i = blockIdx.x * 256 + t;
    if (i < NN) {
        int b = i >> 10;
        int add = (b == 0) ? 0 : sp[b - 1];
        int r = g_rowptr[i] + add;
        g_rowptr[i] = r;
        g_writeptr[i] = r;
    }
    if (i == 0) g_rowptr[NN] = EE;
}

// ======== launch 4 (PROFILED): CSR fill, 4 independent edges/thread ========
__global__ __launch_bounds__(256) void fill4_kernel(const int* __restrict__ src,
                                                    const int* __restrict__ dst) {
    int q = blockIdx.x * blockDim.x + threadIdx.x;   // quad index
    if (q < EE / 4) {
        int4 d = __ldg(reinterpret_cast<const int4*>(dst) + q);
        int4 s = __ldg(reinterpret_cast<const int4*>(src) + q);
        // 4 independent atomics in flight, then dependent stores
        int p0 = atomicAdd(&g_writeptr[d.x], 1);
        int p1 = atomicAdd(&g_writeptr[d.y], 1);
        int p2 = atomicAdd(&g_writeptr[d.z], 1);
        int p3 = atomicAdd(&g_writeptr[d.w], 1);
        g_csr[p0] = s.x;
        g_csr[p1] = s.y;
        g_csr[p2] = s.z;
        g_csr[p3] = s.w;
    }
}

// -------- gather-reduce: uint4 lanes (8 cols each), uint4 index loads --------
// LPN = uint4 lanes per node (row = 8*LPN cols fp16).
template <int LPN>
__global__ __launch_bounds__(256)
void gather4_kernel(const __half2* __restrict__ feat,
                    float* __restrict__ out) {
    int t = blockIdx.x * blockDim.x + threadIdx.x;
    int n = t / LPN;
    int lane = t - n * LPN;
    if (n >= NN) return;
    int s = __ldg(&g_rowptr[n]), e = __ldg(&g_rowptr[n + 1]);
    const uint4* fp = reinterpret_cast<const uint4*>(feat);

    uint4 sv = __ldg(&fp[(size_t)n * LPN + lane]);   // self term
    float2 aA = __half22float2(as_h2(sv.x));
    float2 aB = __half22float2(as_h2(sv.y));
    float2 aC = __half22float2(as_h2(sv.z));
    float2 aD = __half22float2(as_h2(sv.w));

    int j = s;
    // peel to 4-aligned csr index
    int head = (4 - (s & 3)) & 3;
    if (head > e - s) head = e - s;
    for (int q = 0; q < head; q++, j++) {
        int nb = __ldg(&g_csr[j]);
        uint4 v = __ldg(&fp[(size_t)nb * LPN + lane]);
        float2 f;
        f = __half22float2(as_h2(v.x)); aA.x += f.x; aA.y += f.y;
        f = __half22float2(as_h2(v.y)); aB.x += f.x; aB.y += f.y;
        f = __half22float2(as_h2(v.z)); aC.x += f.x; aC.y += f.y;
        f = __half22float2(as_h2(v.w)); aD.x += f.x; aD.y += f.y;
    }
    // aligned body: 4 neighbors per iter, indices via one LDG.128
    for (; j + 4 <= e; j += 4) {
        uint4 ix = __ldg(reinterpret_cast<const uint4*>(g_csr + j));
        uint4 v0 = __ldg(&fp[(size_t)ix.x * LPN + lane]);
        uint4 v1 = __ldg(&fp[(size_t)ix.y * LPN + lane]);
        uint4 v2 = __ldg(&fp[(size_t)ix.z * LPN + lane]);
        uint4 v3 = __ldg(&fp[(size_t)ix.w * LPN + lane]);
        __half2 pA = __hadd2(__hadd2(as_h2(v0.x), as_h2(v1.x)),
                             __hadd2(as_h2(v2.x), as_h2(v3.x)));
        __half2 pB = __hadd2(__hadd2(as_h2(v0.y), as_h2(v1.y)),
                             __hadd2(as_h2(v2.y), as_h2(v3.y)));
        __half2 pC = __hadd2(__hadd2(as_h2(v0.z), as_h2(v1.z)),
                             __hadd2(as_h2(v2.z), as_h2(v3.z)));
        __half2 pD = __hadd2(__hadd2(as_h2(v0.w), as_h2(v1.w)),
                             __hadd2(as_h2(v2.w), as_h2(v3.w)));
        float2 f;
        f = __half22float2(pA); aA.x += f.x; aA.y += f.y;
        f = __half22float2(pB); aB.x += f.x; aB.y += f.y;
        f = __half22float2(pC); aC.x += f.x; aC.y += f.y;
        f = __half22float2(pD); aD.x += f.x; aD.y += f.y;
    }
    // tail
    for (; j < e; j++) {
        int nb = __ldg(&g_csr[j]);
        uint4 v = __ldg(&fp[(size_t)nb * LPN + lane]);
        float2 f;
        f = __half22float2(as_h2(v.x)); aA.x += f.x; aA.y += f.y;
        f = __half22float2(as_h2(v.y)); aB.x += f.x; aB.y += f.y;
        f = __half22float2(as_h2(v.z)); aC.x += f.x; aC.y += f.y;
        f = __half22float2(as_h2(v.w)); aD.x += f.x; aD.y += f.y;
    }

    float4* op = reinterpret_cast<float4*>(out) + (size_t)n * LPN * 2 + lane * 2;
    float4 o0; o0.x = aA.x; o0.y = aA.y; o0.z = aB.x; o0.w = aB.y;
    float4 o1; o1.x = aC.x; o1.y = aC.y; o1.z = aD.x; o1.w = aD.y;
    op[0] = o0; op[1] = o1;
}

// ============ register-blocked fused GIN MLP (unchanged, proven) ============
template <int FIN, int FINP>
__global__ __launch_bounds__(256)
void mlp_kernel(const float* __restrict__ in,
                const float* __restrict__ W1, const float* __restrict__ b1,
                const float* __restrict__ gam, const float* __restrict__ bet,
                const float* __restrict__ rmean, const float* __restrict__ rvar,
                const float* __restrict__ W2, const float* __restrict__ b2,
                int fin_rows,
                __half2* __restrict__ hh_out,
                const int* __restrict__ batch,
                int pool_off) {
    extern __shared__ __align__(16) float smem[];
    float* sW1 = smem;
    float* sW2 = sW1 + FIN * 64;
    float* sB1 = sW2 + 4096;
    float* sB2 = sB1 + 64;
    float* sS  = sB2 + 64;
    float* sT  = sS + 64;
    float* sMid = sT + 64;
    float* sIn = (FIN == 64) ? sMid : (sMid + 128 * 65);

    int tid = threadIdx.x;

    for (int i = tid; i < FIN * 64; i += 256) {
        int k = i >> 6;
        sW1[i] = (k < fin_rows) ? W1[k * 64 + (i & 63)] : 0.0f;
    }
    for (int i = tid; i < 4096; i += 256) sW2[i] = W2[i];
    if (tid < 64) {
        sB1[tid] = b1[tid];
        sB2[tid] = b2[tid];
        float sc = gam[tid] * rsqrtf(rvar[tid] + BN_EPS);
        sS[tid] = sc;
        sT[tid] = bet[tid] - rmean[tid] * sc;
    }

    int base = blockIdx.x * 128;
    for (int i = tid; i < 128 * FIN; i += 256) {
        int r = i / FIN, c = i - r * FIN;
        int n = base + r;
        sIn[r * FINP + c] = (n < NN) ? in[(size_t)n * FIN + c] : 0.0f;
    }
    __syncthreads();

    int tx = tid & 7;
    int ty = tid >> 3;
    int cb = tx * 8;
    int nb = ty * 4;

    unsigned long long acc[4][4];

#pragma unroll
    for (int i = 0; i < 4; i++)
#pragma unroll
        for (int p = 0; p < 4; p++) acc[i][p] = 0ull;

#pragma unroll 4
    for (int k = 0; k < FIN; k++) {
        unsigned long long a2[4];
#pragma unroll
        for (int i = 0; i < 4; i++) {
            float a = sIn[(nb + i) * FINP + k];
            a2[i] = pack2(a, a);
        }
        const ulonglong2* wp = reinterpret_cast<const ulonglong2*>(&sW1[k * 64 + cb]);
        ulonglong2 wA = wp[0], wB = wp[1];
#pragma unroll
        for (int i = 0; i < 4; i++) {
            ffma2(acc[i][0], a2[i], wA.x);
            ffma2(acc[i][1], a2[i], wA.y);
            ffma2(acc[i][2], a2[i], wB.x);
            ffma2(acc[i][3], a2[i], wB.y);
        }
    }
    __syncthreads();

#pragma unroll
    for (int i = 0; i < 4; i++) {
#pragma unroll
        for (int p = 0; p < 4; p++) {
            float u, v;
            unpack2(acc[i][p], u, v);
            int j0 = cb + 2 * p, j1 = j0 + 1;
            sMid[(nb + i) * 65 + j0] = fmaxf(fmaf(u + sB1[j0], sS[j0], sT[j0]), 0.0f);
            sMid[(nb + i) * 65 + j1] = fmaxf(fmaf(v + sB1[j1], sS[j1], sT[j1]), 0.0f);
        }
    }
    __syncthreads();

#pragma unroll
    for (int i = 0; i < 4; i++)
#pragma unroll
        for (int p = 0; p < 4; p++) acc[i][p] = 0ull;

#pragma unroll 4
    for (int k = 0; k < 64; k++) {
        unsigned long long a2[4];
#pragma unroll
        for (int i = 0; i < 4; i++) {
            float a = sMid[(nb + i) * 65 + k];
            a2[i] = pack2(a, a);
        }
        const ulonglong2* wp = reinterpret_cast<const ulonglong2*>(&sW2[k * 64 + cb]);
        ulonglong2 wA = wp[0], wB = wp[1];
#pragma unroll
        for (int i = 0; i < 4; i++) {
            ffma2(acc[i][0], a2[i], wA.x);
            ffma2(acc[i][1], a2[i], wA.y);
            ffma2(acc[i][2], a2[i], wB.x);
            ffma2(acc[i][3], a2[i], wB.y);
        }
    }

#pragma unroll
    for (int i = 0; i < 4; i++) {
        int n = base + nb + i;
        if (n < NN) {
            float o[8];
#pragma unroll
            for (int p = 0; p < 4; p++) {
                float u, v;
                unpack2(acc[i][p], u, v);
                o[2 * p]     = fmaxf(u + sB2[cb + 2 * p], 0.0f);
                o[2 * p + 1] = fmaxf(v + sB2[cb + 2 * p + 1], 0.0f);
            }
            if (hh_out) {
                __half2 hpk[4];
#pragma unroll
                for (int q = 0; q < 4; q++)
                    hpk[q] = __floats2half2_rn(o[2 * q], o[2 * q + 1]);
                *reinterpret_cast<uint4*>(hh_out + (size_t)n * 32 + tx * 4) =
                    *reinterpret_cast<const uint4*>(hpk);
            }
            int b = __ldg(&batch[n]);
            float* pp = &g_pool[b * 192 + pool_off + cb];
            red_add_v4(pp,     o[0], o[1], o[2], o[3]);
            red_add_v4(pp + 4, o[4], o[5], o[6], o[7]);
        }
    }
}

// -------- head --------
__global__ __launch_bounds__(192)
void head_kernel(const float* __restrict__ fc1W, const float* __restrict__ fc1b,
                 const float* __restrict__ fc2W, const float* __restrict__ fc2b,
                 float* __restrict__ out) {
    __shared__ float sP[192];
    __shared__ float sC0[192];
    __shared__ float sC1[192];
    int g = blockIdx.x, j = threadIdx.x;
    sP[j] = g_pool[g * 192 + j];
    __syncthreads();
    float acc = fc1b[j];
#pragma unroll 4
    for (int k = 0; k < 192; k++) acc = fmaf(sP[k], fc1W[k * 192 + j], acc);
    float h = fmaxf(acc, 0.0f);
    sC0[j] = h * fc2W[j * 2 + 0];
    sC1[j] = h * fc2W[j * 2 + 1];
    __syncthreads();
    if (j == 0) {
        float l0 = fc2b[0], l1 = fc2b[1];
        for (int k = 0; k < 192; k++) { l0 += sC0[k]; l1 += sC1[k]; }
        float m = fmaxf(l0, l1);
        float lse = m + logf(expf(l0 - m) + expf(l1 - m));
        out[g * 2 + 0] = l0 - lse;
        out[g * 2 + 1] = l1 - lse;
    }
}

// ---------------------------------------------------------------------
template <typename T>
static T* sym_addr(const void* sym) {
    void* p = nullptr;
    cudaGetSymbolAddress(&p, sym);
    return reinterpret_cast<T*>(p);
}

extern "C" void kernel_launch(void* const* d_in, const int* in_sizes, int n_in,
                              void* d_out, int out_size) {
    const float* x     = (const float*)d_in[0];
    const int*   src   = (const int*)  d_in[1];
    const int*   dst   = (const int*)  d_in[2];
    const int*   batch = (const int*)  d_in[3];

    const float* cp[3][8];
    for (int l = 0; l < 3; l++)
        for (int k = 0; k < 8; k++)
            cp[l][k] = (const float*)d_in[4 + l * 8 + k];
    const float* fc1W = (const float*)d_in[28];
    const float* fc1b = (const float*)d_in[29];
    const float* fc2W = (const float*)d_in[30];
    const float* fc2b = (const float*)d_in[31];
    float* out = (float*)d_out;

    __half2* x16h = sym_addr<__half2>(g_x16h);
    __half2* hh   = sym_addr<__half2>(g_hh);
    float*   agg1 = sym_addr<float>(g_agg1);
    float*   agg  = sym_addr<float>(g_agg);

    const int SMEM64 = (4096 + 4096 + 256 + 128 * 65) * 4;
    const int SMEM16 = (16 * 64 + 4096 + 256 + 128 * 65 + 128 * 17) * 4;
    cudaFuncSetAttribute(mlp_kernel<64, 65>, cudaFuncAttributeMaxDynamicSharedMemorySize, SMEM64);
    cudaFuncSetAttribute(mlp_kernel<16, 17>, cudaFuncAttributeMaxDynamicSharedMemorySize, SMEM16);

    // ---- CSR build: 4 launches ----
    init_count_kernel<<<(EE + 255) / 256, 256>>>(x, dst);
    scan1_kernel<<<NBLK_SCAN, 1024>>>();
    scan23_kernel<<<(NN + 255) / 256, 256>>>();
    fill4_kernel<<<(EE / 4 + 255) / 256, 256>>>(src, dst);   // profiled slot #4

    int mlp_grid = (NN + 127) / 128;

    // ---- layer 1 (16 cols -> LPN=2 uint4 lanes) ----
    gather4_kernel<2><<<(NN * 2 + 255) / 256, 256>>>(x16h, agg1);
    mlp_kernel<16, 17><<<mlp_grid, 256, SMEM16>>>(agg1,
        cp[0][0], cp[0][1], cp[0][2], cp[0][3], cp[0][4], cp[0][5], cp[0][6], cp[0][7],
        FF, hh, batch, 0);

    // ---- layer 2 (64 cols -> LPN=8 uint4 lanes) ----
    gather4_kernel<8><<<(NN * 8 + 255) / 256, 256>>>(hh, agg);
    mlp_kernel<64, 65><<<mlp_grid, 256, SMEM64>>>(agg,
        cp[1][0], cp[1][1], cp[1][2], cp[1][3], cp[1][4], cp[1][5], cp[1][6], cp[1][7],
        64, hh, batch, 64);

    // ---- layer 3 ----
    gather4_kernel<8><<<(NN * 8 + 255) / 256, 256>>>(hh, agg);
    mlp_kernel<64, 65><<<mlp_grid, 256, SMEM64>>>(agg,
        cp[2][0], cp[2][1], cp[2][2], cp[2][3], cp[2][4], cp[2][5], cp[2][6], cp[2][7],
        64, nullptr, batch, 128);

    // ---- head ----
    head_kernel<<<GG, 192>>>(fc1W, fc1b, fc2W, fc2b, out);
}

// round 16
// speedup vs baseline: 2.2158x; 1.4137x over previous
#include <cuda_runtime.h>
#include <cuda_fp16.h>
#include <math.h>

#define NN 100000
#define EE 3200000
#define FF 13
#define GG 512
#define BN_EPS 1e-5f
#define NBLK_SCAN 98

// -------- scratch --------
__device__ __align__(16) __half2 g_x16h[NN * 8];
__device__ __align__(16) __half2 g_hh[NN * 32];
__device__ __align__(16) __half2 g_aggh[NN * 32];
__device__ __align__(16) float g_agg1[NN * 16];
__device__ __align__(16) float g_pool[GG * 192];
__device__ int g_deg[NN];
__device__ int g_rowptr[NN + 1];
__device__ int g_writeptr[NN];
__device__ int g_part[128];
__device__ __align__(16) int g_csr[EE];

// -------- helpers --------
__device__ __forceinline__ unsigned long long pack2(float a, float b) {
    unsigned long long r;
    asm("mov.b64 %0, {%1, %2};" : "=l"(r) : "f"(a), "f"(b));
    return r;
}
__device__ __forceinline__ void unpack2(unsigned long long v, float& a, float& b) {
    asm("mov.b64 {%0, %1}, %2;" : "=f"(a), "=f"(b) : "l"(v));
}
__device__ __forceinline__ void ffma2(unsigned long long& d,
                                      unsigned long long a, unsigned long long b) {
    asm("fma.rn.f32x2 %0, %1, %2, %0;" : "+l"(d) : "l"(a), "l"(b));
}
__device__ __forceinline__ void red_add_v4(float* p, float x, float y, float z, float w) {
    asm volatile("red.global.add.v4.f32 [%0], {%1,%2,%3,%4};"
                 :: "l"(p), "f"(x), "f"(y), "f"(z), "f"(w) : "memory");
}
__device__ __forceinline__ void red_add_v2(float* p, float x, float y) {
    asm volatile("red.global.add.v2.f32 [%0], {%1,%2};"
                 :: "l"(p), "f"(x), "f"(y) : "memory");
}
__device__ __forceinline__ __half2 as_h2(unsigned int u) {
    return *reinterpret_cast<__half2*>(&u);
}
__device__ __forceinline__ unsigned int h2_as_u(__half2 h) {
    return *reinterpret_cast<unsigned int*>(&h);
}
__device__ __forceinline__ unsigned int smem_u32(const void* p) {
    return (unsigned int)__cvta_generic_to_shared(p);
}
__device__ __forceinline__ void ldsm4(unsigned int& r0, unsigned int& r1,
                                      unsigned int& r2, unsigned int& r3,
                                      unsigned int addr) {
    asm volatile("ldmatrix.sync.aligned.m8n8.x4.shared.b16 {%0,%1,%2,%3}, [%4];"
                 : "=r"(r0), "=r"(r1), "=r"(r2), "=r"(r3) : "r"(addr));
}
__device__ __forceinline__ void ldsm4t(unsigned int& r0, unsigned int& r1,
                                       unsigned int& r2, unsigned int& r3,
                                       unsigned int addr) {
    asm volatile("ldmatrix.sync.aligned.m8n8.x4.trans.shared.b16 {%0,%1,%2,%3}, [%4];"
                 : "=r"(r0), "=r"(r1), "=r"(r2), "=r"(r3) : "r"(addr));
}
__device__ __forceinline__ void hmma(float& d0, float& d1, float& d2, float& d3,
                                     unsigned int a0, unsigned int a1,
                                     unsigned int a2, unsigned int a3,
                                     unsigned int e0, unsigned int e1) {
    asm volatile("mma.sync.aligned.m16n8k16.row.col.f32.f16.f16.f32 "
                 "{%0,%1,%2,%3},{%4,%5,%6,%7},{%8,%9},{%0,%1,%2,%3};"
                 : "+f"(d0), "+f"(d1), "+f"(d2), "+f"(d3)
                 : "r"(a0), "r"(a1), "r"(a2), "r"(a3), "r"(e0), "r"(e1));
}

// ======== CSR build ========
__global__ void init_count_kernel(const float* __restrict__ x,
                                  const int* __restrict__ dst) {
    int i = blockIdx.x * blockDim.x + threadIdx.x;
    if (i < NN * 8) {
        int c2 = i & 7, n = i >> 3;
        int c0 = 2 * c2, c1 = c0 + 1;
        float v0 = (c0 < FF) ? x[n * FF + c0] : 0.0f;
        float v1 = (c1 < FF) ? x[n * FF + c1] : 0.0f;
        g_x16h[i] = __floats2half2_rn(v0, v1);
    }
    if (i < GG * 192) g_pool[i] = 0.0f;
    if (i < EE) atomicAdd(&g_deg[__ldg(&dst[i])], 1);
}

__global__ __launch_bounds__(1024) void scan1_kernel() {
    __shared__ int sd[1024];
    int t = threadIdx.x;
    int i = blockIdx.x * 1024 + t;
    int v = 0;
    if (i < NN) { v = g_deg[i]; g_deg[i] = 0; }
    sd[t] = v;
    __syncthreads();
#pragma unroll
    for (int off = 1; off < 1024; off <<= 1) {
        int xx = (t >= off) ? sd[t - off] : 0;
        __syncthreads();
        sd[t] += xx;
        __syncthreads();
    }
    if (i < NN) g_rowptr[i] = sd[t] - v;
    if (t == 1023) g_part[blockIdx.x] = sd[1023];
}

__global__ __launch_bounds__(256) void scan23_kernel() {
    __shared__ int sp[128];
    int t = threadIdx.x;
    if (t < 128) sp[t] = (t < NBLK_SCAN) ? g_part[t] : 0;
    __syncthreads();
#pragma unroll
    for (int off = 1; off < 128; off <<= 1) {
        int xx = 0;
        if (t < 128 && t >= off) xx = sp[t - off];
        __syncthreads();
        if (t < 128) sp[t] += xx;
        __syncthreads();
    }
    int i = blockIdx.x * 256 + t;
    if (i < NN) {
        int blk = i >> 10;
        int add = (blk == 0) ? 0 : sp[blk - 1];
        int r = g_rowptr[i] + add;
        g_rowptr[i] = r;
        g_writeptr[i] = r;
    }
    if (i == 0) g_rowptr[NN] = EE;
}

__global__ __launch_bounds__(256) void fill4_kernel(const int* __restrict__ src,
                                                    const int* __restrict__ dst) {
    int q = blockIdx.x * blockDim.x + threadIdx.x;
    if (q < EE / 4) {
        int4 d = __ldg(reinterpret_cast<const int4*>(dst) + q);
        int4 s = __ldg(reinterpret_cast<const int4*>(src) + q);
        int p0 = atomicAdd(&g_writeptr[d.x], 1);
        int p1 = atomicAdd(&g_writeptr[d.y], 1);
        int p2 = atomicAdd(&g_writeptr[d.z], 1);
        int p3 = atomicAdd(&g_writeptr[d.w], 1);
        g_csr[p0] = s.x;
        g_csr[p1] = s.y;
        g_csr[p2] = s.z;
        g_csr[p3] = s.w;
    }
}

// ======== gather layer 1: 2 uint4 lanes/node, fp32 out ========
__global__ __launch_bounds__(256)
void gather_l1_kernel(float* __restrict__ outp) {
    int t = blockIdx.x * blockDim.x + threadIdx.x;
    int n = t >> 1;
    int lane = t & 1;
    if (n >= NN) return;
    int s = __ldg(&g_rowptr[n]), e = __ldg(&g_rowptr[n + 1]);
    const uint4* fp = reinterpret_cast<const uint4*>(g_x16h);

    uint4 sv = __ldg(&fp[(size_t)n * 2 + lane]);
    float2 aA = __half22float2(as_h2(sv.x));
    float2 aB = __half22float2(as_h2(sv.y));
    float2 aC = __half22float2(as_h2(sv.z));
    float2 aD = __half22float2(as_h2(sv.w));

    int j = s;
    int head = (4 - (s & 3)) & 3;
    if (head > e - s) head = e - s;
    for (int q = 0; q < head; q++) {
        int nb = __ldg(&g_csr[j]);
        j++;
        uint4 v = __ldg(&fp[(size_t)nb * 2 + lane]);
        float2 f;
        f = __half22float2(as_h2(v.x)); aA.x += f.x; aA.y += f.y;
        f = __half22float2(as_h2(v.y)); aB.x += f.x; aB.y += f.y;
        f = __half22float2(as_h2(v.z)); aC.x += f.x; aC.y += f.y;
        f = __half22float2(as_h2(v.w)); aD.x += f.x; aD.y += f.y;
    }
    for (; j + 4 <= e; j += 4) {
        uint4 ix = __ldg(reinterpret_cast<const uint4*>(g_csr + j));
        uint4 v0 = __ldg(&fp[(size_t)ix.x * 2 + lane]);
        uint4 v1 = __ldg(&fp[(size_t)ix.y * 2 + lane]);
        uint4 v2 = __ldg(&fp[(size_t)ix.z * 2 + lane]);
        uint4 v3 = __ldg(&fp[(size_t)ix.w * 2 + lane]);
        __half2 pA = __hadd2(__hadd2(as_h2(v0.x), as_h2(v1.x)), __hadd2(as_h2(v2.x), as_h2(v3.x)));
        __half2 pB = __hadd2(__hadd2(as_h2(v0.y), as_h2(v1.y)), __hadd2(as_h2(v2.y), as_h2(v3.y)));
        __half2 pC = __hadd2(__hadd2(as_h2(v0.z), as_h2(v1.z)), __hadd2(as_h2(v2.z), as_h2(v3.z)));
        __half2 pD = __hadd2(__hadd2(as_h2(v0.w), as_h2(v1.w)), __hadd2(as_h2(v2.w), as_h2(v3.w)));
        float2 f;
        f = __half22float2(pA); aA.x += f.x; aA.y += f.y;
        f = __half22float2(pB); aB.x += f.x; aB.y += f.y;
        f = __half22float2(pC); aC.x += f.x; aC.y += f.y;
        f = __half22float2(pD); aD.x += f.x; aD.y += f.y;
    }
    for (; j < e; j++) {
        int nb = __ldg(&g_csr[j]);
        uint4 v = __ldg(&fp[(size_t)nb * 2 + lane]);
        float2 f;
        f = __half22float2(as_h2(v.x)); aA.x += f.x; aA.y += f.y;
        f = __half22float2(as_h2(v.y)); aB.x += f.x; aB.y += f.y;
        f = __half22float2(as_h2(v.z)); aC.x += f.x; aC.y += f.y;
        f = __half22float2(as_h2(v.w)); aD.x += f.x; aD.y += f.y;
    }
    float4* op = reinterpret_cast<float4*>(outp) + (size_t)n * 4 + lane * 2;
    float4 o0; o0.x = aA.x; o0.y = aA.y; o0.z = aB.x; o0.w = aB.y;
    float4 o1; o1.x = aC.x; o1.y = aC.y; o1.z = aD.x; o1.w = aD.y;
    op[0] = o0;
    op[1] = o1;
}

// ======== gather H=64: 8 uint4 lanes/node, fp16 out ========
__global__ __launch_bounds__(256)
void gather_h64_kernel(const __half2* __restrict__ feat, __half2* __restrict__ outp) {
    int t = blockIdx.x * blockDim.x + threadIdx.x;
    int n = t >> 3;
    int lane = t & 7;
    if (n >= NN) return;
    int s = __ldg(&g_rowptr[n]), e = __ldg(&g_rowptr[n + 1]);
    const uint4* fp = reinterpret_cast<const uint4*>(feat);

    uint4 sv = __ldg(&fp[(size_t)n * 8 + lane]);
    float2 aA = __half22float2(as_h2(sv.x));
    float2 aB = __half22float2(as_h2(sv.y));
    float2 aC = __half22float2(as_h2(sv.z));
    float2 aD = __half22float2(as_h2(sv.w));

    int j = s;
    int head = (4 - (s & 3)) & 3;
    if (head > e - s) head = e - s;
    for (int q = 0; q < head; q++) {
        int nb = __ldg(&g_csr[j]);
        j++;
        uint4 v = __ldg(&fp[(size_t)nb * 8 + lane]);
        float2 f;
        f = __half22float2(as_h2(v.x)); aA.x += f.x; aA.y += f.y;
        f = __half22float2(as_h2(v.y)); aB.x += f.x; aB.y += f.y;
        f = __half22float2(as_h2(v.z)); aC.x += f.x; aC.y += f.y;
        f = __half22float2(as_h2(v.w)); aD.x += f.x; aD.y += f.y;
    }
    for (; j + 4 <= e; j += 4) {
        uint4 ix = __ldg(reinterpret_cast<const uint4*>(g_csr + j));
        uint4 v0 = __ldg(&fp[(size_t)ix.x * 8 + lane]);
        uint4 v1 = __ldg(&fp[(size_t)ix.y * 8 + lane]);
        uint4 v2 = __ldg(&fp[(size_t)ix.z * 8 + lane]);
        uint4 v3 = __ldg(&fp[(size_t)ix.w * 8 + lane]);
        __half2 pA = __hadd2(__hadd2(as_h2(v0.x), as_h2(v1.x)), __hadd2(as_h2(v2.x), as_h2(v3.x)));
        __half2 pB = __hadd2(__hadd2(as_h2(v0.y), as_h2(v1.y)), __hadd2(as_h2(v2.y), as_h2(v3.y)));
        __half2 pC = __hadd2(__hadd2(as_h2(v0.z), as_h2(v1.z)), __hadd2(as_h2(v2.z), as_h2(v3.z)));
        __half2 pD = __hadd2(__hadd2(as_h2(v0.w), as_h2(v1.w)), __hadd2(as_h2(v2.w), as_h2(v3.w)));
        float2 f;
        f = __half22float2(pA); aA.x += f.x; aA.y += f.y;
        f = __half22float2(pB); aB.x += f.x; aB.y += f.y;
        f = __half22float2(pC); aC.x += f.x; aC.y += f.y;
        f = __half22float2(pD); aD.x += f.x; aD.y += f.y;
    }
    for (; j < e; j++) {
        int nb = __ldg(&g_csr[j]);
        uint4 v = __ldg(&fp[(size_t)nb * 8 + lane]);
        float2 f;
        f = __half22float2(as_h2(v.x)); aA.x += f.x; aA.y += f.y;
        f = __half22float2(as_h2(v.y)); aB.x += f.x; aB.y += f.y;
        f = __half22float2(as_h2(v.z)); aC.x += f.x; aC.y += f.y;
        f = __half22float2(as_h2(v.w)); aD.x += f.x; aD.y += f.y;
    }
    uint4 o;
    o.x = h2_as_u(__floats2half2_rn(aA.x, aA.y));
    o.y = h2_as_u(__floats2half2_rn(aB.x, aB.y));
    o.z = h2_as_u(__floats2half2_rn(aC.x, aC.y));
    o.w = h2_as_u(__floats2half2_rn(aD.x, aD.y));
    reinterpret_cast<uint4*>(outp)[(size_t)n * 8 + lane] = o;
}

// ======== tensor-core MLP for H=64 layers (128 nodes/block, 8 warps) ========
__global__ __launch_bounds__(256)
void mlp64_mma_kernel(const __half2* inh,
                      const float* Wa, const float* bias1,
                      const float* gam, const float* bet,
                      const float* rmean, const float* rvar,
                      const float* Wb, const float* bias2,
                      __half2* hh_out, const int* batch, int pool_off) {
    __shared__ __align__(16) __half sA[128 * 72];
    __shared__ __align__(16) __half sW1h[64 * 72];
    __shared__ __align__(16) __half sW2h[64 * 72];
    __shared__ float sB1[64];
    __shared__ float sB2[64];
    __shared__ float sS[64];
    __shared__ float sT[64];

    int tid = threadIdx.x;
    int wid = tid >> 5;
    int lane = tid & 31;
    int base = blockIdx.x * 128;

    for (int idx = tid; idx < 1024; idx += 256) {
        int r = idx >> 3;
        int cc = idx & 7;
        int n = base + r;
        uint4 v;
        v.x = 0u; v.y = 0u; v.z = 0u; v.w = 0u;
        if (n < NN) v = *(reinterpret_cast<const uint4*>(inh) + (size_t)n * 8 + cc);
        *reinterpret_cast<uint4*>(&sA[r * 72 + cc * 8]) = v;
    }
    for (int idx = tid; idx < 2048; idx += 256) {
        int r = idx >> 5;
        int c2 = idx & 31;
        float2 w1v = reinterpret_cast<const float2*>(Wa)[idx];
        float2 w2v = reinterpret_cast<const float2*>(Wb)[idx];
        *reinterpret_cast<__half2*>(&sW1h[r * 72 + c2 * 2]) = __floats2half2_rn(w1v.x, w1v.y);
        *reinterpret_cast<__half2*>(&sW2h[r * 72 + c2 * 2]) = __floats2half2_rn(w2v.x, w2v.y);
    }
    if (tid < 64) {
        sB1[tid] = bias1[tid];
        sB2[tid] = bias2[tid];
        float sc = gam[tid] * rsqrtf(rvar[tid] + BN_EPS);
        sS[tid] = sc;
        sT[tid] = bet[tid] - rmean[tid] * sc;
    }
    __syncthreads();

    int xr = lane & 15;
    int xc = (lane >> 4) * 8;
    unsigned int aBase = smem_u32(sA) + (unsigned int)(((wid * 16 + xr) * 72 + xc) * 2);
    unsigned int w1Base = smem_u32(sW1h) + (unsigned int)((xr * 72 + xc) * 2);
    unsigned int w2Base = smem_u32(sW2h) + (unsigned int)((xr * 72 + xc) * 2);

    float cfr[32];

    // ---- stage 1 ----
#pragma unroll
    for (int i = 0; i < 32; i++) cfr[i] = 0.0f;
#pragma unroll
    for (int k = 0; k < 4; k++) {
        unsigned int fa0, fa1, fa2, fa3;
        ldsm4(fa0, fa1, fa2, fa3, aBase + (unsigned int)(k * 32));
#pragma unroll
        for (int p = 0; p < 4; p++) {
            unsigned int wr0, wr1, wr2, wr3;
            ldsm4t(wr0, wr1, wr2, wr3, w1Base + (unsigned int)((k * 16 * 72 + p * 16) * 2));
            hmma(cfr[p * 8 + 0], cfr[p * 8 + 1], cfr[p * 8 + 2], cfr[p * 8 + 3],
                 fa0, fa1, fa2, fa3, wr0, wr1);
            hmma(cfr[p * 8 + 4], cfr[p * 8 + 5], cfr[p * 8 + 6], cfr[p * 8 + 7],
                 fa0, fa1, fa2, fa3, wr2, wr3);
        }
    }
    __syncthreads();

    // BN + relu -> mid (fp16) back into sA
    {
        int r0 = wid * 16 + (lane >> 2);
        int tc = lane & 3;
#pragma unroll
        for (int nt = 0; nt < 8; nt++) {
            int col = nt * 8 + 2 * tc;
            float m00 = fmaxf(fmaf(cfr[nt * 4 + 0] + sB1[col], sS[col], sT[col]), 0.0f);
            float m01 = fmaxf(fmaf(cfr[nt * 4 + 1] + sB1[col + 1], sS[col + 1], sT[col + 1]), 0.0f);
            float m10 = fmaxf(fmaf(cfr[nt * 4 + 2] + sB1[col], sS[col], sT[col]), 0.0f);
            float m11 = fmaxf(fmaf(cfr[nt * 4 + 3] + sB1[col + 1], sS[col + 1], sT[col + 1]), 0.0f);
            *reinterpret_cast<__half2*>(&sA[r0 * 72 + col]) = __floats2half2_rn(m00, m01);
            *reinterpret_cast<__half2*>(&sA[(r0 + 8) * 72 + col]) = __floats2half2_rn(m10, m11);
        }
    }
    __syncthreads();

    // ---- stage 2 ----
#pragma unroll
    for (int i = 0; i < 32; i++) cfr[i] = 0.0f;
#pragma unroll
    for (int k = 0; k < 4; k++) {
        unsigned int fa0, fa1, fa2, fa3;
        ldsm4(fa0, fa1, fa2, fa3, aBase + (unsigned int)(k * 32));
#pragma unroll
        for (int p = 0; p < 4; p++) {
            unsigned int wr0, wr1, wr2, wr3;
            ldsm4t(wr0, wr1, wr2, wr3, w2Base + (unsigned int)((k * 16 * 72 + p * 16) * 2));
            hmma(cfr[p * 8 + 0], cfr[p * 8 + 1], cfr[p * 8 + 2], cfr[p * 8 + 3],
                 fa0, fa1, fa2, fa3, wr0, wr1);
            hmma(cfr[p * 8 + 4], cfr[p * 8 + 5], cfr[p * 8 + 6], cfr[p * 8 + 7],
                 fa0, fa1, fa2, fa3, wr2, wr3);
        }
    }

    // ---- epilogue ----
    {
        int r0 = wid * 16 + (lane >> 2);
        int tc = lane & 3;
        int n0 = base + r0;
        int n1 = n0 + 8;
        bool ok0 = (n0 < NN);
        bool ok1 = (n1 < NN);
        int bb0 = ok0 ? __ldg(&batch[n0]) : 0;
        int bb1 = ok1 ? __ldg(&batch[n1]) : 0;
        float* pp0 = &g_pool[bb0 * 192 + pool_off];
        float* pp1 = &g_pool[bb1 * 192 + pool_off];
#pragma unroll
        for (int nt = 0; nt < 8; nt++) {
            int col = nt * 8 + 2 * tc;
            float o00 = fmaxf(cfr[nt * 4 + 0] + sB2[col], 0.0f);
            float o01 = fmaxf(cfr[nt * 4 + 1] + sB2[col + 1], 0.0f);
            float o10 = fmaxf(cfr[nt * 4 + 2] + sB2[col], 0.0f);
            float o11 = fmaxf(cfr[nt * 4 + 3] + sB2[col + 1], 0.0f);
            if (ok0) {
                if (hh_out) hh_out[(size_t)n0 * 32 + (col >> 1)] = __floats2half2_rn(o00, o01);
                red_add_v2(pp0 + col, o00, o01);
            }
            if (ok1) {
                if (hh_out) hh_out[(size_t)n1 * 32 + (col >> 1)] = __floats2half2_rn(o10, o11);
                red_add_v2(pp1 + col, o10, o11);
            }
        }
    }
}

// ======== layer-1 MLP (f32x2 path, proven) ========
__global__ __launch_bounds__(256)
void mlp16_kernel(const float* __restrict__ inp,
                  const float* __restrict__ Wa, const float* __restrict__ bias1,
                  const float* __restrict__ gam, const float* __restrict__ bet,
                  const float* __restrict__ rmean, const float* __restrict__ rvar,
                  const float* __restrict__ Wb, const float* __restrict__ bias2,
                  __half2* __restrict__ hh_out,
                  const int* __restrict__ batch, int pool_off) {
    extern __shared__ __align__(16) float smem[];
    float* sW1 = smem;
    float* sW2 = sW1 + 1024;
    float* sB1 = sW2 + 4096;
    float* sB2 = sB1 + 64;
    float* sS = sB2 + 64;
    float* sT = sS + 64;
    float* sMid = sT + 64;
    float* sIn = sMid + 128 * 65;

    int tid = threadIdx.x;

    for (int i = tid; i < 1024; i += 256) {
        int k = i >> 6;
        sW1[i] = (k < FF) ? Wa[k * 64 + (i & 63)] : 0.0f;
    }
    for (int i = tid; i < 4096; i += 256) sW2[i] = Wb[i];
    if (tid < 64) {
        sB1[tid] = bias1[tid];
        sB2[tid] = bias2[tid];
        float sc = gam[tid] * rsqrtf(rvar[tid] + BN_EPS);
        sS[tid] = sc;
        sT[tid] = bet[tid] - rmean[tid] * sc;
    }

    int base = blockIdx.x * 128;
    for (int i = tid; i < 128 * 16; i += 256) {
        int r = i >> 4;
        int cc = i & 15;
        int n = base + r;
        sIn[r * 17 + cc] = (n < NN) ? inp[(size_t)n * 16 + cc] : 0.0f;
    }
    __syncthreads();

    int tx = tid & 7;
    int ty = tid >> 3;
    int cb = tx * 8;
    int nb = ty * 4;

    unsigned long long acc[4][4];
#pragma unroll
    for (int i = 0; i < 4; i++) {
#pragma unroll
        for (int p = 0; p < 4; p++) acc[i][p] = 0ull;
    }

#pragma unroll 4
    for (int k = 0; k < 16; k++) {
        unsigned long long a2[4];
#pragma unroll
        for (int i = 0; i < 4; i++) {
            float a = sIn[(nb + i) * 17 + k];
            a2[i] = pack2(a, a);
        }
        const ulonglong2* wp = reinterpret_cast<const ulonglong2*>(&sW1[k * 64 + cb]);
        ulonglong2 wA = wp[0];
        ulonglong2 wB = wp[1];
#pragma unroll
        for (int i = 0; i < 4; i++) {
            ffma2(acc[i][0], a2[i], wA.x);
            ffma2(acc[i][1], a2[i], wA.y);
            ffma2(acc[i][2], a2[i], wB.x);
            ffma2(acc[i][3], a2[i], wB.y);
        }
    }
    __syncthreads();

#pragma unroll
    for (int i = 0; i < 4; i++) {
#pragma unroll
        for (int p = 0; p < 4; p++) {
            float u, v;
            unpack2(acc[i][p], u, v);
            int j0 = cb + 2 * p;
            int j1 = j0 + 1;
            sMid[(nb + i) * 65 + j0] = fmaxf(fmaf(u + sB1[j0], sS[j0], sT[j0]), 0.0f);
            sMid[(nb + i) * 65 + j1] = fmaxf(fmaf(v + sB1[j1], sS[j1], sT[j1]), 0.0f);
        }
    }
    __syncthreads();

#pragma unroll
    for (int i = 0; i < 4; i++) {
#pragma unroll
        for (int p = 0; p < 4; p++) acc[i][p] = 0ull;
    }

#pragma unroll 4
    for (int k = 0; k < 64; k++) {
        unsigned long long a2[4];
#pragma unroll
        for (int i = 0; i < 4; i++) {
            float a = sMid[(nb + i) * 65 + k];
            a2[i] = pack2(a, a);
        }
        const ulonglong2* wp = reinterpret_cast<const ulonglong2*>(&sW2[k * 64 + cb]);
        ulonglong2 wA = wp[0];
        ulonglong2 wB = wp[1];
#pragma unroll
        for (int i = 0; i < 4; i++) {
            ffma2(acc[i][0], a2[i], wA.x);
            ffma2(acc[i][1], a2[i], wA.y);
            ffma2(acc[i][2], a2[i], wB.x);
            ffma2(acc[i][3], a2[i], wB.y);
        }
    }

#pragma unroll
    for (int i = 0; i < 4; i++) {
        int n = base + nb + i;
        if (n < NN) {
            float o[8];
#pragma unroll
            for (int p = 0; p < 4; p++) {
                float u, v;
                unpack2(acc[i][p], u, v);
                o[2 * p] = fmaxf(u + sB2[cb + 2 * p], 0.0f);
                o[2 * p + 1] = fmaxf(v + sB2[cb + 2 * p + 1], 0.0f);
            }
            __half2 hpk[4];
#pragma unroll
            for (int q = 0; q < 4; q++) hpk[q] = __floats2half2_rn(o[2 * q], o[2 * q + 1]);
            *reinterpret_cast<uint4*>(hh_out + (size_t)n * 32 + tx * 4) =
                *reinterpret_cast<const uint4*>(hpk);
            int bb = __ldg(&batch[n]);
            float* pp = &g_pool[bb * 192 + pool_off + cb];
            red_add_v4(pp, o[0], o[1], o[2], o[3]);
            red_add_v4(pp + 4, o[4], o[5], o[6], o[7]);
        }
    }
}

// ======== head ========
__global__ __launch_bounds__(192)
void head_kernel(const float* __restrict__ fc1W, const float* __restrict__ fc1b,
                 const float* __restrict__ fc2W, const float* __restrict__ fc2b,
                 float* __restrict__ outp) {
    __shared__ float sP[192];
    __shared__ float sC0[192];
    __shared__ float sC1[192];
    int g = blockIdx.x;
    int j = threadIdx.x;
    sP[j] = g_pool[g * 192 + j];
    __syncthreads();
    float acc = fc1b[j];
#pragma unroll 4
    for (int k = 0; k < 192; k++) acc = fmaf(sP[k], fc1W[k * 192 + j], acc);
    float h = fmaxf(acc, 0.0f);
    sC0[j] = h * fc2W[j * 2 + 0];
    sC1[j] = h * fc2W[j * 2 + 1];
    __syncthreads();
    if (j == 0) {
        float l0 = fc2b[0];
        float l1 = fc2b[1];
        for (int k = 0; k < 192; k++) {
            l0 += sC0[k];
            l1 += sC1[k];
        }
        float m = fmaxf(l0, l1);
        float lse = m + logf(expf(l0 - m) + expf(l1 - m));
        outp[g * 2 + 0] = l0 - lse;
        outp[g * 2 + 1] = l1 - lse;
    }
}

// ---------------------------------------------------------------------
extern "C" void kernel_launch(void* const* d_in, const int* in_sizes, int n_in,
                              void* d_out, int out_size) {
    const float* x = (const float*)d_in[0];
    const int* src = (const int*)d_in[1];
    const int* dst = (const int*)d_in[2];
    const int* batch = (const int*)d_in[3];

    const float* cp[3][8];
    for (int l = 0; l < 3; l++) {
        for (int k = 0; k < 8; k++) {
            cp[l][k] = (const float*)d_in[4 + l * 8 + k];
        }
    }
    const float* fc1W = (const float*)d_in[28];
    const float* fc1b = (const float*)d_in[29];
    const float* fc2W = (const float*)d_in[30];
    const float* fc2b = (const float*)d_in[31];
    float* outp = (float*)d_out;

    void* pa = 0;
    void* pb = 0;
    void* pc = 0;
    cudaGetSymbolAddress(&pa, g_hh);
    cudaGetSymbolAddress(&pb, g_aggh);
    cudaGetSymbolAddress(&pc, g_agg1);
    __half2* hh = (__half2*)pa;
    __half2* aggh = (__half2*)pb;
    float* agg1 = (float*)pc;

    const int SMEM16 = (1024 + 4096 + 256 + 128 * 65 + 128 * 17) * 4;
    cudaFuncSetAttribute(mlp16_kernel, cudaFuncAttributeMaxDynamicSharedMemorySize, SMEM16);

    // CSR build
    init_count_kernel<<<(EE + 255) / 256, 256>>>(x, dst);
    scan1_kernel<<<NBLK_SCAN, 1024>>>();
    scan23_kernel<<<(NN + 255) / 256, 256>>>();
    fill4_kernel<<<(EE / 4 + 255) / 256, 256>>>(src, dst);

    int mlp_grid = (NN + 127) / 128;

    // layer 1
    gather_l1_kernel<<<(NN * 2 + 255) / 256, 256>>>(agg1);
    mlp16_kernel<<<mlp_grid, 256, SMEM16>>>(agg1,
        cp[0][0], cp[0][1], cp[0][2], cp[0][3], cp[0][4], cp[0][5], cp[0][6], cp[0][7],
        hh, batch, 0);

    // layer 2
    gather_h64_kernel<<<(NN * 8 + 255) / 256, 256>>>(hh, aggh);
    mlp64_mma_kernel<<<mlp_grid, 256>>>(aggh,
        cp[1][0], cp[1][1], cp[1][2], cp[1][3], cp[1][4], cp[1][5], cp[1][6], cp[1][7],
        hh, batch, 64);

    // layer 3
    gather_h64_kernel<<<(NN * 8 + 255) / 256, 256>>>(hh, aggh);
    mlp64_mma_kernel<<<mlp_grid, 256>>>(aggh,
        cp[2][0], cp[2][1], cp[2][2], cp[2][3], cp[2][4], cp[2][5], cp[2][6], cp[2][7],
        (__half2*)0, batch, 128);

    // head
    head_kernel<<<GG, 192>>>(fc1W, fc1b, fc2W, fc2b, outp);
}